// round 2
// baseline (speedup 1.0000x reference)
#include <cuda_runtime.h>
#include <cuda_bf16.h>
#include <math.h>

// ---- problem constants ----
#define NPTS   4096
#define NVIEW  6
#define SDIM   128
#define KTOP   5
#define RADIUS 0.01f
#define R2F    (RADIUS*RADIUS)
#define ZNEARF 0.01f
#define ZFARF  100.0f
#define NPIX   (NVIEW*SDIM*SDIM)   // 98304
#define MSLOT  32

// ---- scratch (static __device__; no allocation) ----
__device__ int   g_cnt[NPIX];
__device__ float g_z[NPIX*MSLOT];
__device__ float g_w[NPIX*MSLOT];
__device__ float g_c[NPIX*MSLOT];
__device__ float g_col[NPTS];

struct Cams {
    float R[NVIEW][9];   // row-major, columns are x,y,z basis
    float T[NVIEW][3];
};

// ---- kernel 1: colors = sigmoid(init + displace) ----
__global__ void colors_kernel(const float* __restrict__ ic,
                              const float* __restrict__ dp,
                              float* __restrict__ out_tail) {
    int i = blockIdx.x * blockDim.x + threadIdx.x;
    if (i < NPTS) {
        float c = 1.0f / (1.0f + __expf(-(ic[i] + dp[i])));
        g_col[i]    = c;
        out_tail[i] = c;
    }
}

// ---- kernel 2: scatter points into per-pixel slot lists ----
__global__ void scatter_kernel(const float* __restrict__ pcd, Cams cams) {
    int i = blockIdx.x * blockDim.x + threadIdx.x;
    if (i >= NPTS) return;
    float p0 = pcd[3*i+0], p1 = pcd[3*i+1], p2 = pcd[3*i+2];
    float col = g_col[i];

    #pragma unroll
    for (int v = 0; v < NVIEW; v++) {
        const float* R = cams.R[v];
        const float* T = cams.T[v];
        float px = p0*R[0] + p1*R[3] + p2*R[6] + T[0];
        float py = p0*R[1] + p1*R[4] + p2*R[7] + T[1];
        float pz = p0*R[2] + p1*R[5] + p2*R[8] + T[2];
        if (!(pz > ZNEARF && pz < ZFARF)) continue;

        // pixel center along x (col j) / y (row r): (S-1-2j)/S. Candidate band:
        // |t - j| < S*R/2 = 0.64 (use 0.66 slack; exact test is d2 < R2 below)
        float tx = 0.5f * ((float)(SDIM-1) - (float)SDIM * px);
        float ty = 0.5f * ((float)(SDIM-1) - (float)SDIM * py);
        int jlo = (int)ceilf (tx - 0.66f); if (jlo < 0) jlo = 0;
        int jhi = (int)floorf(tx + 0.66f); if (jhi > SDIM-1) jhi = SDIM-1;
        int ilo = (int)ceilf (ty - 0.66f); if (ilo < 0) ilo = 0;
        int ihi = (int)floorf(ty + 0.66f); if (ihi > SDIM-1) ihi = SDIM-1;

        for (int r = ilo; r <= ihi; r++) {
            float dy = (float)(SDIM-1-2*r) * (1.0f/(float)SDIM) - py;
            float dy2 = dy * dy;
            for (int c = jlo; c <= jhi; c++) {
                float dx = (float)(SDIM-1-2*c) * (1.0f/(float)SDIM) - px;
                float d2 = dx*dx + dy2;
                if (d2 < R2F) {
                    int pix = (v*SDIM + r)*SDIM + c;
                    int n = atomicAdd(&g_cnt[pix], 1);
                    if (n < MSLOT) {
                        g_z[pix*MSLOT + n] = pz;
                        g_w[pix*MSLOT + n] = 1.0f - d2 * (1.0f/R2F);
                        g_c[pix*MSLOT + n] = col;
                    }
                }
            }
        }
    }
}

// ---- kernel 3: per-pixel K-nearest selection + alpha compositing ----
__global__ void composite_kernel(float* __restrict__ out) {
    int pix = blockIdx.x * blockDim.x + threadIdx.x;
    if (pix >= NPIX) return;
    int n = g_cnt[pix];
    if (n > MSLOT) n = MSLOT;

    float acc = 0.0f, trans = 1.0f;
    unsigned used = 0u;
    int kmax = (n < KTOP) ? n : KTOP;
    for (int k = 0; k < kmax; k++) {
        float bz = 3.0e38f; int bi = -1;
        for (int e = 0; e < n; e++) {
            if (used & (1u << e)) continue;
            float z = g_z[pix*MSLOT + e];
            if (z < bz) { bz = z; bi = e; }
        }
        used |= (1u << bi);
        float w = g_w[pix*MSLOT + bi];
        acc  += w * trans * g_c[pix*MSLOT + bi];
        trans *= (1.0f - w);
    }
    float* o = out + (size_t)pix * 3;
    o[0] = acc; o[1] = acc; o[2] = acc;
}

// ---- host: replicate PyTorch3D look_at_view_transform ----
static void compute_cams(Cams& cams) {
    const double views[NVIEW] = {45.0, 90.0, 135.0, 225.0, 270.0, 315.0};
    const double elev = 15.0 * M_PI / 180.0;
    const double dist = 1.5;
    for (int v = 0; v < NVIEW; v++) {
        double az = views[v] * M_PI / 180.0;
        double C[3] = { dist*cos(elev)*sin(az), dist*sin(elev), dist*cos(elev)*cos(az) };
        double z[3] = { -C[0]/dist, -C[1]/dist, -C[2]/dist };
        // x = normalize(cross(up=(0,1,0), z)) = normalize((z2, 0, -z0))
        double x[3] = { z[2], 0.0, -z[0] };
        double xn = sqrt(x[0]*x[0] + x[1]*x[1] + x[2]*x[2]);
        x[0]/=xn; x[1]/=xn; x[2]/=xn;
        // y = normalize(cross(z, x))
        double y[3] = { z[1]*x[2]-z[2]*x[1], z[2]*x[0]-z[0]*x[2], z[0]*x[1]-z[1]*x[0] };
        double yn = sqrt(y[0]*y[0] + y[1]*y[1] + y[2]*y[2]);
        y[0]/=yn; y[1]/=yn; y[2]/=yn;
        for (int r = 0; r < 3; r++) {
            cams.R[v][r*3+0] = (float)x[r];
            cams.R[v][r*3+1] = (float)y[r];
            cams.R[v][r*3+2] = (float)z[r];
        }
        cams.T[v][0] = (float)(-(C[0]*x[0] + C[1]*x[1] + C[2]*x[2]));
        cams.T[v][1] = (float)(-(C[0]*y[0] + C[1]*y[1] + C[2]*y[2]));
        cams.T[v][2] = (float)(-(C[0]*z[0] + C[1]*z[1] + C[2]*z[2]));
    }
}

extern "C" void kernel_launch(void* const* d_in, const int* in_sizes, int n_in,
                              void* d_out, int out_size) {
    const float* pcd = (const float*)d_in[0];
    const float* ic  = (const float*)d_in[1];
    const float* dp  = (const float*)d_in[2];
    float* out = (float*)d_out;

    Cams cams;
    compute_cams(cams);

    void* cnt_ptr = nullptr;
    cudaGetSymbolAddress(&cnt_ptr, g_cnt);
    cudaMemsetAsync(cnt_ptr, 0, NPIX * sizeof(int));

    colors_kernel<<<(NPTS + 255) / 256, 256>>>(ic, dp, out + (size_t)NPIX * 3);
    scatter_kernel<<<(NPTS + 255) / 256, 256>>>(pcd, cams);
    composite_kernel<<<(NPIX + 255) / 256, 256>>>(out);
}

// round 3
// speedup vs baseline: 1.0129x; 1.0129x over previous
#include <cuda_runtime.h>
#include <cuda_bf16.h>
#include <math.h>

// ---- problem constants ----
#define NPTS   4096
#define NVIEW  6
#define SDIM   128
#define KTOP   5
#define RADIUS 0.01f
#define R2F    (RADIUS*RADIUS)
#define ZNEARF 0.01f
#define ZFARF  100.0f
#define NPIX   (NVIEW*SDIM*SDIM)   // 98304
#define MSLOT  32

// ---- scratch (static __device__; no allocation) ----
__device__ int   g_cnt[NPIX];
__device__ float g_z[NPIX*MSLOT];
__device__ float g_w[NPIX*MSLOT];
__device__ float g_c[NPIX*MSLOT];
__device__ float g_col[NPTS];

struct Cams {
    float R[NVIEW][9];   // row-major, columns are x,y,z basis
    float T[NVIEW][3];
};

// ---- kernel 1: colors = sigmoid(init + displace) ----
__global__ void colors_kernel(const float* __restrict__ ic,
                              const float* __restrict__ dp,
                              float* __restrict__ out_tail) {
    int i = blockIdx.x * blockDim.x + threadIdx.x;
    if (i < NPTS) {
        float c = 1.0f / (1.0f + __expf(-(ic[i] + dp[i])));
        g_col[i]    = c;
        out_tail[i] = c;
    }
}

// ---- kernel 2: scatter points into per-pixel slot lists ----
__global__ void scatter_kernel(const float* __restrict__ pcd, Cams cams) {
    int i = blockIdx.x * blockDim.x + threadIdx.x;
    if (i >= NPTS) return;
    float p0 = pcd[3*i+0], p1 = pcd[3*i+1], p2 = pcd[3*i+2];
    float col = g_col[i];

    #pragma unroll
    for (int v = 0; v < NVIEW; v++) {
        const float* R = cams.R[v];
        const float* T = cams.T[v];
        float px = p0*R[0] + p1*R[3] + p2*R[6] + T[0];
        float py = p0*R[1] + p1*R[4] + p2*R[7] + T[1];
        float pz = p0*R[2] + p1*R[5] + p2*R[8] + T[2];
        if (!(pz > ZNEARF && pz < ZFARF)) continue;

        // pixel center along x (col j) / y (row r): (S-1-2j)/S. Candidate band:
        // |t - j| < S*R/2 = 0.64 (use 0.66 slack; exact test is d2 < R2 below)
        float tx = 0.5f * ((float)(SDIM-1) - (float)SDIM * px);
        float ty = 0.5f * ((float)(SDIM-1) - (float)SDIM * py);
        int jlo = (int)ceilf (tx - 0.66f); if (jlo < 0) jlo = 0;
        int jhi = (int)floorf(tx + 0.66f); if (jhi > SDIM-1) jhi = SDIM-1;
        int ilo = (int)ceilf (ty - 0.66f); if (ilo < 0) ilo = 0;
        int ihi = (int)floorf(ty + 0.66f); if (ihi > SDIM-1) ihi = SDIM-1;

        for (int r = ilo; r <= ihi; r++) {
            float dy = (float)(SDIM-1-2*r) * (1.0f/(float)SDIM) - py;
            float dy2 = dy * dy;
            for (int c = jlo; c <= jhi; c++) {
                float dx = (float)(SDIM-1-2*c) * (1.0f/(float)SDIM) - px;
                float d2 = dx*dx + dy2;
                if (d2 < R2F) {
                    int pix = (v*SDIM + r)*SDIM + c;
                    int n = atomicAdd(&g_cnt[pix], 1);
                    if (n < MSLOT) {
                        g_z[pix*MSLOT + n] = pz;
                        g_w[pix*MSLOT + n] = 1.0f - d2 * (1.0f/R2F);
                        g_c[pix*MSLOT + n] = col;
                    }
                }
            }
        }
    }
}

// ---- kernel 3: per-pixel K-nearest selection + alpha compositing ----
__global__ void composite_kernel(float* __restrict__ out) {
    int pix = blockIdx.x * blockDim.x + threadIdx.x;
    if (pix >= NPIX) return;
    int n = g_cnt[pix];
    if (n > MSLOT) n = MSLOT;

    float acc = 0.0f, trans = 1.0f;
    unsigned used = 0u;
    int kmax = (n < KTOP) ? n : KTOP;
    for (int k = 0; k < kmax; k++) {
        float bz = 3.0e38f; int bi = -1;
        for (int e = 0; e < n; e++) {
            if (used & (1u << e)) continue;
            float z = g_z[pix*MSLOT + e];
            if (z < bz) { bz = z; bi = e; }
        }
        used |= (1u << bi);
        float w = g_w[pix*MSLOT + bi];
        acc  += w * trans * g_c[pix*MSLOT + bi];
        trans *= (1.0f - w);
    }
    float* o = out + (size_t)pix * 3;
    o[0] = acc; o[1] = acc; o[2] = acc;
}

// ---- host: replicate PyTorch3D look_at_view_transform ----
static void compute_cams(Cams& cams) {
    const double views[NVIEW] = {45.0, 90.0, 135.0, 225.0, 270.0, 315.0};
    const double elev = 15.0 * M_PI / 180.0;
    const double dist = 1.5;
    for (int v = 0; v < NVIEW; v++) {
        double az = views[v] * M_PI / 180.0;
        double C[3] = { dist*cos(elev)*sin(az), dist*sin(elev), dist*cos(elev)*cos(az) };
        double z[3] = { -C[0]/dist, -C[1]/dist, -C[2]/dist };
        // x = normalize(cross(up=(0,1,0), z)) = normalize((z2, 0, -z0))
        double x[3] = { z[2], 0.0, -z[0] };
        double xn = sqrt(x[0]*x[0] + x[1]*x[1] + x[2]*x[2]);
        x[0]/=xn; x[1]/=xn; x[2]/=xn;
        // y = normalize(cross(z, x))
        double y[3] = { z[1]*x[2]-z[2]*x[1], z[2]*x[0]-z[0]*x[2], z[0]*x[1]-z[1]*x[0] };
        double yn = sqrt(y[0]*y[0] + y[1]*y[1] + y[2]*y[2]);
        y[0]/=yn; y[1]/=yn; y[2]/=yn;
        for (int r = 0; r < 3; r++) {
            cams.R[v][r*3+0] = (float)x[r];
            cams.R[v][r*3+1] = (float)y[r];
            cams.R[v][r*3+2] = (float)z[r];
        }
        cams.T[v][0] = (float)(-(C[0]*x[0] + C[1]*x[1] + C[2]*x[2]));
        cams.T[v][1] = (float)(-(C[0]*y[0] + C[1]*y[1] + C[2]*y[2]));
        cams.T[v][2] = (float)(-(C[0]*z[0] + C[1]*z[1] + C[2]*z[2]));
    }
}

extern "C" void kernel_launch(void* const* d_in, const int* in_sizes, int n_in,
                              void* d_out, int out_size) {
    const float* pcd = (const float*)d_in[0];
    const float* ic  = (const float*)d_in[1];
    const float* dp  = (const float*)d_in[2];
    float* out = (float*)d_out;

    Cams cams;
    compute_cams(cams);

    void* cnt_ptr = nullptr;
    cudaGetSymbolAddress(&cnt_ptr, g_cnt);
    cudaMemsetAsync(cnt_ptr, 0, NPIX * sizeof(int));

    colors_kernel<<<(NPTS + 255) / 256, 256>>>(ic, dp, out + (size_t)NPIX * 3);
    scatter_kernel<<<(NPTS + 255) / 256, 256>>>(pcd, cams);
    composite_kernel<<<(NPIX + 255) / 256, 256>>>(out);
}